// round 15
// baseline (speedup 1.0000x reference)
#include <cuda_runtime.h>
#include <cstdint>

// GrokkingSNN: B=32768, hidden=512, p=97, 15 steps.
//   cur1[b,j] = P1[x0,j] + P2[x1,j] + b1[j], P = E @ W1half.T
//   9409 distinct pairs -> simulate per pair; mem2 = S @ W2.T + b2*G.
// R15: phase-1 recurrence rebalanced across pipes: 2 FFMA (fma pipe) +
//      FSET/FSEL (alu pipe) per step via pre-subtracted drive cm = c - thr1.
//      Everything else identical to R14.

#define HIDDEN 512
#define PDIM 97
#define NPAIR (PDIM * PDIM)   // 9409
#define NSTEPS 15
#define UPITCH 104

#define NP 32       // pairs per CTA (pair kernel)
#define SHP 260     // S bf16x2 pitch (u32/row)
#define NTILE 13    // n8 tiles covering p=97
#define NKS 32      // k16 slices covering HIDDEN

// precompute tiling
#define PJT 64      // j per block
#define PVT 16      // v per block
#define W1PIT 129   // W1 tile pitch in float4 (conflict-free LDS.128)

__device__ float g_P[2 * PDIM * HIDDEN];
__device__ float g_U[NPAIR * UPITCH];
// W2 bf16 hi/lo in mma B-fragment order: [(nt*32+ks)*32+lane]{2}
__device__ unsigned int g_Wh[NTILE * NKS * 32 * 2];
__device__ unsigned int g_Wl[NTILE * NKS * 32 * 2];

typedef unsigned long long ull;
typedef unsigned int u32;

__device__ __forceinline__ float fsetgt(float a, float b) {
    float d; asm("set.gt.f32.f32 %0, %1, %2;" : "=f"(d) : "f"(a), "f"(b));
    return d;   // 1.0f if a>b else 0.0f
}
__device__ __forceinline__ u32 bfpack(float hif, float lof) {
    u32 d; asm("cvt.rn.bf16x2.f32 %0, %1, %2;" : "=r"(d) : "f"(hif), "f"(lof));
    return d;
}
__device__ __forceinline__ float bflo(u32 d) { return __uint_as_float(d << 16); }
__device__ __forceinline__ float bfhi(u32 d) { return __uint_as_float(d & 0xFFFF0000u); }

__device__ __forceinline__ void mma_bf16(float* c, const u32* a, u32 b0, u32 b1) {
    asm("mma.sync.aligned.m16n8k16.row.col.f32.bf16.bf16.f32 "
        "{%0,%1,%2,%3}, {%4,%5,%6,%7}, {%8,%9}, {%0,%1,%2,%3};"
        : "+f"(c[0]), "+f"(c[1]), "+f"(c[2]), "+f"(c[3])
        : "r"(a[0]), "r"(a[1]), "r"(a[2]), "r"(a[3]), "r"(b0), "r"(b1));
}
__device__ __forceinline__ void cpa16(u32 smem_addr, const void* gptr) {
    asm volatile("cp.async.cg.shared.global [%0], [%1], 16;"
                 :: "r"(smem_addr), "l"(gptr));
}

// ---------------------------------------------------------------------------
// Kernel A: P[s][v][j] = sum_k E[v][k] * W1[j][s*512+k]   (identical to R14)
// Also converts W2 -> bf16 hi/lo fragment tables.
// ---------------------------------------------------------------------------
__global__ void __launch_bounds__(256, 1) precompute_kernel(
    const float* __restrict__ E, const float* __restrict__ W1,
    const float* __restrict__ W2)
{
    extern __shared__ float4 psm[];
    float4* Es4  = psm;                        // [PVT][128]
    float4* W1s4 = psm + PVT * (HIDDEN / 4);   // [PJT][W1PIT]

    const int jt = blockIdx.x, vt = blockIdx.y, s = blockIdx.z;
    const int tid  = threadIdx.x;
    const int lane = tid & 31;    // j within tile (and j+32)
    const int grp  = tid >> 5;    // warp -> 2 v rows
    const int vbase = vt * PVT;

    const float4* E4  = reinterpret_cast<const float4*>(E);
    const float4* W14 = reinterpret_cast<const float4*>(W1);  // row stride 256

    const u32 sE = (u32)__cvta_generic_to_shared(Es4);
    const u32 sW = (u32)__cvta_generic_to_shared(W1s4);

#pragma unroll
    for (int r = 0; r < 8; r++) {
        int idx = tid + 256 * r;
        int vv = idx >> 7;
        int c4 = idx & 127;
        int v  = vbase + vv;
        int vl = (v < PDIM) ? v : (PDIM - 1);
        cpa16(sE + (u32)(vv * 128 + c4) * 16, E4 + (size_t)vl * 128 + c4);
    }
#pragma unroll 8
    for (int r = 0; r < 32; r++) {
        int idx = tid + 256 * r;
        int row = idx >> 7;
        int c4  = idx & 127;
        cpa16(sW + (u32)(row * W1PIT + c4) * 16,
              W14 + (size_t)(jt * PJT + row) * 256 + s * 128 + c4);
    }
    asm volatile("cp.async.commit_group;");

    // W2 -> bf16 hi/lo fragment tables (overlaps cp.async drain)
    {
        const int bid = blockIdx.x + 8 * (blockIdx.y + 7 * blockIdx.z);
        const int gtid = bid * 256 + tid;
        if (gtid < NTILE * NKS * 32) {
            const int lane_ = gtid & 31;
            const int ks_   = (gtid >> 5) & 31;
            const int nt_   = gtid >> 10;          // 0..12
            const int p  = nt_ * 8 + (lane_ >> 2);
            const int tq = lane_ & 3;
#pragma unroll
            for (int i = 0; i < 2; i++) {
                const int kp = ks_ * 8 + tq + 4 * i;   // k-pair index
                float2 w = make_float2(0.f, 0.f);
                if (p < PDIM)
                    w = *reinterpret_cast<const float2*>(W2 + p * HIDDEN + 2 * kp);
                u32 h = bfpack(w.y, w.x);
                u32 l = bfpack(w.y - bfhi(h), w.x - bflo(h));
                g_Wh[gtid * 2 + i] = h;
                g_Wl[gtid * 2 + i] = l;
            }
        }
    }

    asm volatile("cp.async.wait_group 0;");
    __syncthreads();

    float acc[2][2];
#pragma unroll
    for (int u = 0; u < 2; u++) { acc[u][0] = 0.f; acc[u][1] = 0.f; }

#pragma unroll 4
    for (int k4 = 0; k4 < HIDDEN / 4; k4++) {
        float4 w0 = W1s4[lane * W1PIT + k4];
        float4 w1 = W1s4[(lane + 32) * W1PIT + k4];
#pragma unroll
        for (int u = 0; u < 2; u++) {
            float4 e = Es4[(grp * 2 + u) * 128 + k4];
            acc[u][0] = fmaf(e.x, w0.x, acc[u][0]);
            acc[u][0] = fmaf(e.y, w0.y, acc[u][0]);
            acc[u][0] = fmaf(e.z, w0.z, acc[u][0]);
            acc[u][0] = fmaf(e.w, w0.w, acc[u][0]);
            acc[u][1] = fmaf(e.x, w1.x, acc[u][1]);
            acc[u][1] = fmaf(e.y, w1.y, acc[u][1]);
            acc[u][1] = fmaf(e.z, w1.z, acc[u][1]);
            acc[u][1] = fmaf(e.w, w1.w, acc[u][1]);
        }
    }

    const int j0 = jt * PJT + lane;
#pragma unroll
    for (int u = 0; u < 2; u++) {
        int vg = vbase + grp * 2 + u;
        if (vg < PDIM) {
            g_P[(s * PDIM + vg) * HIDDEN + j0]      = acc[u][0];
            g_P[(s * PDIM + vg) * HIDDEN + j0 + 32] = acc[u][1];
        }
    }
}

// ---------------------------------------------------------------------------
// Kernel B: 295 CTAs x 32 pairs, 256 threads, 2 CTAs/SM.
// Phase 1: scalar LIF sim, select-form recurrence (2 FFMA + FSET + FSEL).
// Phase 2: m-merged 3xBF16-split mma (identical to R14).
// ---------------------------------------------------------------------------
__global__ void __launch_bounds__(256, 2) pair_kernel(
    const float* __restrict__ b1, const float* __restrict__ b2,
    const float* __restrict__ pbeta1, const float* __restrict__ pbeta2,
    const float* __restrict__ pthr1)
{
    extern __shared__ u32 smu[];
    u32* Sh = smu;                 // [NP][SHP]
    u32* Sl = Sh + NP * SHP;       // [NP][SHP]

    const float beta1 = fminf(fmaxf(__ldg(pbeta1), 0.1f), 0.9f);
    const float beta2 = fminf(fmaxf(__ldg(pbeta2), 0.1f), 0.9f);
    const float thr1  = fmaxf(__ldg(pthr1), 0.1f);

    const int tid = threadIdx.x;

    // ---------------- phase 1: simulate 32 pairs x 512 h (scalar) -----------
    {
        const int q   = tid >> 3;   // pair slot 0..31
        const int sub = tid & 7;    // h-eighth
        int pp = blockIdx.x * NP + q;
        if (pp >= NPAIR) pp = 0;
        const int a = pp / PDIM;
        const int b = pp - a * PDIM;
        const float4* p1  = reinterpret_cast<const float4*>(g_P + a * HIDDEN);
        const float4* p2  = reinterpret_cast<const float4*>(g_P + (PDIM + b) * HIDDEN);
        const float4* b14 = reinterpret_cast<const float4*>(b1);

        float4 n1 = __ldg(p1 + sub), n2 = __ldg(p2 + sub), nb = __ldg(b14 + sub);

#pragma unroll 1
        for (int o = 0; o < 16; o++) {
            const float4 v1 = n1, v2 = n2, vb = nb;
            if (o < 15) {
                const int h4n = sub + 8 * (o + 1);
                n1 = __ldg(p1 + h4n);
                n2 = __ldg(p2 + h4n);
                nb = __ldg(b14 + h4n);
            }
            // c = (p1 + p2) + b1 ; cm = c - thr1 (pre-subtracted spiked drive)
            float c[4], cm[4], dr[4], m[4], S[4], spf[4];
            c[0] = __fadd_rn(__fadd_rn(v1.x, v2.x), vb.x);
            c[1] = __fadd_rn(__fadd_rn(v1.y, v2.y), vb.y);
            c[2] = __fadd_rn(__fadd_rn(v1.z, v2.z), vb.z);
            c[3] = __fadd_rn(__fadd_rn(v1.w, v2.w), vb.w);
#pragma unroll
            for (int u = 0; u < 4; u++) {
                cm[u] = __fsub_rn(c[u], thr1);
                dr[u] = c[u];
                m[u] = 0.f; S[u] = 0.f; spf[u] = 0.f;
            }
#pragma unroll
            for (int t = 0; t < NSTEPS; t++) {
#pragma unroll
                for (int u = 0; u < 4; u++) {
                    // mem = beta1*mem + (cur1 - reset*thr1): select-form drive
                    float mm = __fmaf_rn(beta1, m[u], dr[u]);
                    spf[u] = fsetgt(mm, thr1);
                    dr[u] = (spf[u] != 0.f) ? cm[u] : c[u];   // FSEL (alu pipe)
                    m[u] = mm;
                    S[u] = __fmaf_rn(beta2, S[u], spf[u]);
                }
            }
            u32 h0 = bfpack(S[1], S[0]);
            u32 l0 = bfpack(S[1] - bfhi(h0), S[0] - bflo(h0));
            u32 h1 = bfpack(S[3], S[2]);
            u32 l1 = bfpack(S[3] - bfhi(h1), S[2] - bflo(h1));
            const int h4 = sub + 8 * o;
            *reinterpret_cast<ull*>(Sh + q * SHP + 2 * h4) =
                (ull)h0 | ((ull)h1 << 32);
            *reinterpret_cast<ull*>(Sl + q * SHP + 2 * h4) =
                (ull)l0 | ((ull)l1 << 32);
        }
    }
    __syncthreads();   // the ONLY barrier

    // ---------------- phase 2: tensor GEMM (3xBF16 split, m-merged) ---------
    const int warp = tid >> 5;   // nt = warp and warp + 8
    const int lane = tid & 31;
    const int g  = lane >> 2;
    const int t  = lane & 3;

    const ull* WhG = reinterpret_cast<const ull*>(g_Wh);
    const ull* WlG = reinterpret_cast<const ull*>(g_Wl);

    float acc[2][2][4];   // [m-tile][nt-slot][4]
#pragma unroll
    for (int mt = 0; mt < 2; mt++)
#pragma unroll
        for (int sl = 0; sl < 2; sl++)
#pragma unroll
            for (int e = 0; e < 4; e++) acc[mt][sl][e] = 0.f;

#pragma unroll 2
    for (int ks = 0; ks < NKS; ks++) {
        const int kpg = ks * 8 + t;
        u32 ah[2][4], al[2][4];
#pragma unroll
        for (int mt = 0; mt < 2; mt++) {
            const int prow = mt * 16 + g;
            ah[mt][0] = Sh[prow * SHP + kpg];
            ah[mt][1] = Sh[(prow + 8) * SHP + kpg];
            ah[mt][2] = Sh[prow * SHP + kpg + 4];
            ah[mt][3] = Sh[(prow + 8) * SHP + kpg + 4];
            al[mt][0] = Sl[prow * SHP + kpg];
            al[mt][1] = Sl[(prow + 8) * SHP + kpg];
            al[mt][2] = Sl[prow * SHP + kpg + 4];
            al[mt][3] = Sl[(prow + 8) * SHP + kpg + 4];
        }
#pragma unroll
        for (int sl = 0; sl < 2; sl++) {
            const int nt = warp + 8 * sl;
            if (nt < NTILE) {
                const int fi = (nt * NKS + ks) * 32 + lane;
                ull wh = __ldg(WhG + fi);
                ull wl = __ldg(WlG + fi);
                u32 bh0 = (u32)wh, bh1 = (u32)(wh >> 32);
                u32 bl0 = (u32)wl, bl1 = (u32)(wl >> 32);
#pragma unroll
                for (int mt = 0; mt < 2; mt++) {
                    mma_bf16(acc[mt][sl], ah[mt], bh0, bh1);   // hi*hi
                    mma_bf16(acc[mt][sl], al[mt], bh0, bh1);   // lo*hi
                    mma_bf16(acc[mt][sl], ah[mt], bl0, bl1);   // hi*lo
                }
            }
        }
    }

    float G = 0.0f;
#pragma unroll
    for (int t2 = 0; t2 < NSTEPS; t2++) G = __fadd_rn(__fmul_rn(beta2, G), 1.0f);

#pragma unroll
    for (int mt = 0; mt < 2; mt++) {
#pragma unroll
        for (int sl = 0; sl < 2; sl++) {
            const int nt = warp + 8 * sl;
            if (nt < NTILE) {
#pragma unroll
                for (int e = 0; e < 4; e++) {
                    const int pp = blockIdx.x * NP + mt * 16 + g + (e >> 1) * 8;
                    const int n = nt * 8 + 2 * t + (e & 1);
                    if (pp < NPAIR && n < PDIM)
                        g_U[pp * UPITCH + n] = acc[mt][sl][e] + __ldg(b2 + n) * G;
                }
            }
        }
    }
}

// ---------------------------------------------------------------------------
// Kernel C: out[b,:] = U[pair(b),:]. One warp per output row.
// ---------------------------------------------------------------------------
__global__ void __launch_bounds__(256) scatter_kernel(
    const int* __restrict__ x, float* __restrict__ out, int B)
{
    int warp = blockIdx.x * 8 + (threadIdx.x >> 5);
    int lane = threadIdx.x & 31;
    if (warp >= B) return;
    int x0 = __ldg(x + 2 * warp);
    int x1 = __ldg(x + 2 * warp + 1);
    const float* u = g_U + (size_t)(x0 * PDIM + x1) * UPITCH;
    float* o = out + (size_t)warp * PDIM;
#pragma unroll
    for (int j = 0; j < 3; j++) o[lane + 32 * j] = u[lane + 32 * j];
    if (lane == 0) o[96] = u[96];
}

// ---------------------------------------------------------------------------
extern "C" void kernel_launch(void* const* d_in, const int* in_sizes, int n_in,
                              void* d_out, int out_size)
{
    const int*   x     = (const int*)  d_in[0];
    const float* E     = (const float*)d_in[1];
    const float* W1    = (const float*)d_in[2];
    const float* b1    = (const float*)d_in[3];
    const float* W2    = (const float*)d_in[4];
    const float* b2    = (const float*)d_in[5];
    const float* beta1 = (const float*)d_in[6];
    const float* beta2 = (const float*)d_in[7];
    const float* thr1  = (const float*)d_in[8];
    // thr2 unused in forward (lif2 reset='none'; output is mem2).

    const int B = in_sizes[0] / 2;

    const int psmemB = (PVT * (HIDDEN / 4) + PJT * W1PIT) * (int)sizeof(float4); // 164864
    cudaFuncSetAttribute(precompute_kernel,
                         cudaFuncAttributeMaxDynamicSharedMemorySize, psmemB);

    const int smemB = 2 * NP * SHP * (int)sizeof(u32);   // 66560 B
    cudaFuncSetAttribute(pair_kernel, cudaFuncAttributeMaxDynamicSharedMemorySize, smemB);

    precompute_kernel<<<dim3(8, 7, 2), 256, psmemB>>>(E, W1, W2);
    pair_kernel<<<(NPAIR + NP - 1) / NP, 256, smemB>>>(b1, b2, beta1, beta2, thr1);
    scatter_kernel<<<(B + 7) / 8, 256>>>(x, (float*)d_out, B);
}

// round 17
// speedup vs baseline: 1.0383x; 1.0383x over previous
#include <cuda_runtime.h>
#include <cstdint>

// GrokkingSNN: B=32768, hidden=512, p=97, 15 steps.
//   cur1[b,j] = P1[x0,j] + P2[x1,j] + b1[j], P = E @ W1half.T
//   9409 distinct pairs -> simulate per pair; mem2 = S @ W2.T + b2*G.
// R17: R16 with the ABsm load bug fixed (256-thread block must loop to fill
//      384 table entries). Phase-1: FFMA + @p FADD + SETP + @p OR per step;
//      S recovered from A[lo8]+B[hi7] smem tables (<=2ulp vs exact Horner).

#define HIDDEN 512
#define PDIM 97
#define NPAIR (PDIM * PDIM)   // 9409
#define NSTEPS 15
#define UPITCH 104

#define NP 32       // pairs per CTA (pair kernel)
#define SHP 260     // S bf16x2 pitch (u32/row)
#define NTILE 13    // n8 tiles covering p=97
#define NKS 32      // k16 slices covering HIDDEN
#define WFRAG (NTILE * NKS * 32)   // 13312 fragment slots

// precompute tiling
#define PJT 64      // j per block
#define PVT 16      // v per block
#define W1PIT 129   // W1 tile pitch in float4 (conflict-free LDS.128)

__device__ float g_P[2 * PDIM * HIDDEN];
__device__ float g_U[NPAIR * UPITCH];
// W2 bf16 hi/lo in mma B-fragment order: [(nt*32+ks)*32+lane]{2}
__device__ unsigned int g_Wh[WFRAG * 2];
__device__ unsigned int g_Wl[WFRAG * 2];
__device__ float g_AB[384];   // A[256] (steps 0..7), B[128] (steps 8..14)

typedef unsigned long long ull;
typedef unsigned int u32;

__device__ __forceinline__ u32 bfpack(float hif, float lof) {
    u32 d; asm("cvt.rn.bf16x2.f32 %0, %1, %2;" : "=r"(d) : "f"(hif), "f"(lof));
    return d;
}
__device__ __forceinline__ float bflo(u32 d) { return __uint_as_float(d << 16); }
__device__ __forceinline__ float bfhi(u32 d) { return __uint_as_float(d & 0xFFFF0000u); }

__device__ __forceinline__ void mma_bf16(float* c, const u32* a, u32 b0, u32 b1) {
    asm("mma.sync.aligned.m16n8k16.row.col.f32.bf16.bf16.f32 "
        "{%0,%1,%2,%3}, {%4,%5,%6,%7}, {%8,%9}, {%0,%1,%2,%3};"
        : "+f"(c[0]), "+f"(c[1]), "+f"(c[2]), "+f"(c[3])
        : "r"(a[0]), "r"(a[1]), "r"(a[2]), "r"(a[3]), "r"(b0), "r"(b1));
}
__device__ __forceinline__ void cpa16(u32 smem_addr, const void* gptr) {
    asm volatile("cp.async.cg.shared.global [%0], [%1], 16;"
                 :: "r"(smem_addr), "l"(gptr));
}

// 15-step LIF recurrence -> spike bitmask. Per step:
//   m = fma(beta1, m, c); @p m = add(m, -thr1); setp p = m > thr1; @p bits |= 1<<t
// @p add with p=1 is RN(m - thr1) == fma(1.0, -thr1, m)  -> bit-identical to R14.
#define LIF_STEP(MASK) \
    "fma.rn.f32 %0, %2, %0, %3;\n\t" \
    "@p add.rn.f32 %0, %0, %4;\n\t" \
    "setp.gt.f32 p, %0, %5;\n\t" \
    "@p or.b32 %1, %1, " MASK ";\n\t"

__device__ __forceinline__ u32 lif_bits(float c, float beta1, float nthr1, float thr1) {
    float m = 0.f;
    u32 bits = 0;
    asm("{\n\t"
        ".reg .pred p;\n\t"
        "setp.ne.f32 p, %5, %5;\n\t"   // p = false
        LIF_STEP("1")     LIF_STEP("2")    LIF_STEP("4")    LIF_STEP("8")
        LIF_STEP("16")    LIF_STEP("32")   LIF_STEP("64")   LIF_STEP("128")
        LIF_STEP("256")   LIF_STEP("512")  LIF_STEP("1024") LIF_STEP("2048")
        LIF_STEP("4096")  LIF_STEP("8192") LIF_STEP("16384")
        "}"
        : "+f"(m), "+r"(bits)
        : "f"(beta1), "f"(c), "f"(nthr1), "f"(thr1));
    return bits;
}

// ---------------------------------------------------------------------------
// Kernel A: P[s][v][j] = sum_k E[v][k] * W1[j][s*512+k]   (R14 core)
// Also converts W2 -> bf16 hi/lo fragment tables and builds the S tables.
// ---------------------------------------------------------------------------
__global__ void __launch_bounds__(256, 1) precompute_kernel(
    const float* __restrict__ E, const float* __restrict__ W1,
    const float* __restrict__ W2, const float* __restrict__ pbeta2)
{
    extern __shared__ float4 psm[];
    float4* Es4  = psm;                        // [PVT][128]
    float4* W1s4 = psm + PVT * (HIDDEN / 4);   // [PJT][W1PIT]

    const int jt = blockIdx.x, vt = blockIdx.y, s = blockIdx.z;
    const int tid  = threadIdx.x;
    const int lane = tid & 31;    // j within tile (and j+32)
    const int grp  = tid >> 5;    // warp -> 2 v rows
    const int vbase = vt * PVT;

    const float4* E4  = reinterpret_cast<const float4*>(E);
    const float4* W14 = reinterpret_cast<const float4*>(W1);  // row stride 256

    const u32 sE = (u32)__cvta_generic_to_shared(Es4);
    const u32 sW = (u32)__cvta_generic_to_shared(W1s4);

#pragma unroll
    for (int r = 0; r < 8; r++) {
        int idx = tid + 256 * r;
        int vv = idx >> 7;
        int c4 = idx & 127;
        int v  = vbase + vv;
        int vl = (v < PDIM) ? v : (PDIM - 1);
        cpa16(sE + (u32)(vv * 128 + c4) * 16, E4 + (size_t)vl * 128 + c4);
    }
#pragma unroll 8
    for (int r = 0; r < 32; r++) {
        int idx = tid + 256 * r;
        int row = idx >> 7;
        int c4  = idx & 127;
        cpa16(sW + (u32)(row * W1PIT + c4) * 16,
              W14 + (size_t)(jt * PJT + row) * 256 + s * 128 + c4);
    }
    asm volatile("cp.async.commit_group;");

    // side work (overlaps cp.async drain): W2 fragments + S tables
    {
        const int bid = blockIdx.x + 8 * (blockIdx.y + 7 * blockIdx.z);
        const int gtid = bid * 256 + tid;
        if (gtid < WFRAG) {
            const int lane_ = gtid & 31;
            const int ks_   = (gtid >> 5) & 31;
            const int nt_   = gtid >> 10;          // 0..12
            const int p  = nt_ * 8 + (lane_ >> 2);
            const int tq = lane_ & 3;
#pragma unroll
            for (int i = 0; i < 2; i++) {
                const int kp = ks_ * 8 + tq + 4 * i;   // k-pair index
                float2 w = make_float2(0.f, 0.f);
                if (p < PDIM)
                    w = *reinterpret_cast<const float2*>(W2 + p * HIDDEN + 2 * kp);
                u32 h = bfpack(w.y, w.x);
                u32 l = bfpack(w.y - bfhi(h), w.x - bflo(h));
                g_Wh[gtid * 2 + i] = h;
                g_Wl[gtid * 2 + i] = l;
            }
        } else if (gtid < WFRAG + 384) {
            const float b2c = fminf(fmaxf(__ldg(pbeta2), 0.1f), 0.9f);
            const int i = gtid - WFRAG;
            float S = 0.f;
            if (i < 256) {
#pragma unroll
                for (int t = 0; t < NSTEPS; t++) {
                    float spk = (t < 8) ? (float)((i >> t) & 1) : 0.f;
                    S = __fmaf_rn(b2c, S, spk);
                }
            } else {
                const int j = i - 256;
#pragma unroll
                for (int t = 0; t < NSTEPS; t++) {
                    float spk = (t >= 8) ? (float)((j >> (t - 8)) & 1) : 0.f;
                    S = __fmaf_rn(b2c, S, spk);
                }
            }
            g_AB[i] = S;
        }
    }

    asm volatile("cp.async.wait_group 0;");
    __syncthreads();

    float acc[2][2];
#pragma unroll
    for (int u = 0; u < 2; u++) { acc[u][0] = 0.f; acc[u][1] = 0.f; }

#pragma unroll 4
    for (int k4 = 0; k4 < HIDDEN / 4; k4++) {
        float4 w0 = W1s4[lane * W1PIT + k4];
        float4 w1 = W1s4[(lane + 32) * W1PIT + k4];
#pragma unroll
        for (int u = 0; u < 2; u++) {
            float4 e = Es4[(grp * 2 + u) * 128 + k4];
            acc[u][0] = fmaf(e.x, w0.x, acc[u][0]);
            acc[u][0] = fmaf(e.y, w0.y, acc[u][0]);
            acc[u][0] = fmaf(e.z, w0.z, acc[u][0]);
            acc[u][0] = fmaf(e.w, w0.w, acc[u][0]);
            acc[u][1] = fmaf(e.x, w1.x, acc[u][1]);
            acc[u][1] = fmaf(e.y, w1.y, acc[u][1]);
            acc[u][1] = fmaf(e.z, w1.z, acc[u][1]);
            acc[u][1] = fmaf(e.w, w1.w, acc[u][1]);
        }
    }

    const int j0 = jt * PJT + lane;
#pragma unroll
    for (int u = 0; u < 2; u++) {
        int vg = vbase + grp * 2 + u;
        if (vg < PDIM) {
            g_P[(s * PDIM + vg) * HIDDEN + j0]      = acc[u][0];
            g_P[(s * PDIM + vg) * HIDDEN + j0 + 32] = acc[u][1];
        }
    }
}

// ---------------------------------------------------------------------------
// Kernel B: 295 CTAs x 32 pairs, 256 threads, 2 CTAs/SM.
// Phase 1: LIF sim via predicated bitmask loop; S = A[lo8] + B[hi7] (smem).
// Phase 2: m-merged 3xBF16-split mma (identical to R14).
// ---------------------------------------------------------------------------
__global__ void __launch_bounds__(256, 2) pair_kernel(
    const float* __restrict__ b1, const float* __restrict__ b2,
    const float* __restrict__ pbeta1, const float* __restrict__ pbeta2,
    const float* __restrict__ pthr1)
{
    extern __shared__ u32 smu[];
    u32* Sh = smu;                 // [NP][SHP]
    u32* Sl = Sh + NP * SHP;       // [NP][SHP]
    float* ABsm = reinterpret_cast<float*>(Sl + NP * SHP);   // [384]

    const float beta1 = fminf(fmaxf(__ldg(pbeta1), 0.1f), 0.9f);
    const float beta2 = fminf(fmaxf(__ldg(pbeta2), 0.1f), 0.9f);
    const float thr1  = fmaxf(__ldg(pthr1), 0.1f);
    const float nthr1 = -thr1;

    const int tid = threadIdx.x;

    // FIX (R16 bug): 256 threads must loop to fill all 384 table entries.
    for (int i = tid; i < 384; i += 256) ABsm[i] = g_AB[i];
    __syncthreads();

    // ---------------- phase 1: simulate 32 pairs x 512 h --------------------
    {
        const int q   = tid >> 3;   // pair slot 0..31
        const int sub = tid & 7;    // h-eighth
        int pp = blockIdx.x * NP + q;
        if (pp >= NPAIR) pp = 0;
        const int a = pp / PDIM;
        const int b = pp - a * PDIM;
        const float4* p1  = reinterpret_cast<const float4*>(g_P + a * HIDDEN);
        const float4* p2  = reinterpret_cast<const float4*>(g_P + (PDIM + b) * HIDDEN);
        const float4* b14 = reinterpret_cast<const float4*>(b1);

        float4 n1 = __ldg(p1 + sub), n2 = __ldg(p2 + sub), nb = __ldg(b14 + sub);

#pragma unroll 1
        for (int o = 0; o < 16; o++) {
            const float4 v1 = n1, v2 = n2, vb = nb;
            if (o < 15) {
                const int h4n = sub + 8 * (o + 1);
                n1 = __ldg(p1 + h4n);
                n2 = __ldg(p2 + h4n);
                nb = __ldg(b14 + h4n);
            }
            // c = (p1 + p2) + b1  (same rounding as all rounds)
            float c[4];
            c[0] = __fadd_rn(__fadd_rn(v1.x, v2.x), vb.x);
            c[1] = __fadd_rn(__fadd_rn(v1.y, v2.y), vb.y);
            c[2] = __fadd_rn(__fadd_rn(v1.z, v2.z), vb.z);
            c[3] = __fadd_rn(__fadd_rn(v1.w, v2.w), vb.w);

            u32 bt[4];
#pragma unroll
            for (int u = 0; u < 4; u++)
                bt[u] = lif_bits(c[u], beta1, nthr1, thr1);

            float S[4];
#pragma unroll
            for (int u = 0; u < 4; u++)
                S[u] = __fadd_rn(ABsm[bt[u] & 255], ABsm[256 + (bt[u] >> 8)]);

            u32 h0 = bfpack(S[1], S[0]);
            u32 l0 = bfpack(S[1] - bfhi(h0), S[0] - bflo(h0));
            u32 h1 = bfpack(S[3], S[2]);
            u32 l1 = bfpack(S[3] - bfhi(h1), S[2] - bflo(h1));
            const int h4 = sub + 8 * o;
            *reinterpret_cast<ull*>(Sh + q * SHP + 2 * h4) =
                (ull)h0 | ((ull)h1 << 32);
            *reinterpret_cast<ull*>(Sl + q * SHP + 2 * h4) =
                (ull)l0 | ((ull)l1 << 32);
        }
    }
    __syncthreads();

    // ---------------- phase 2: tensor GEMM (3xBF16 split, m-merged) ---------
    const int warp = tid >> 5;   // nt = warp and warp + 8
    const int lane = tid & 31;
    const int g  = lane >> 2;
    const int t  = lane & 3;

    const ull* WhG = reinterpret_cast<const ull*>(g_Wh);
    const ull* WlG = reinterpret_cast<const ull*>(g_Wl);

    float acc[2][2][4];   // [m-tile][nt-slot][4]
#pragma unroll
    for (int mt = 0; mt < 2; mt++)
#pragma unroll
        for (int sl = 0; sl < 2; sl++)
#pragma unroll
            for (int e = 0; e < 4; e++) acc[mt][sl][e] = 0.f;

#pragma unroll 2
    for (int ks = 0; ks < NKS; ks++) {
        const int kpg = ks * 8 + t;
        u32 ah[2][4], al[2][4];
#pragma unroll
        for (int mt = 0; mt < 2; mt++) {
            const int prow = mt * 16 + g;
            ah[mt][0] = Sh[prow * SHP + kpg];
            ah[mt][1] = Sh[(prow + 8) * SHP + kpg];
            ah[mt][2] = Sh[prow * SHP + kpg + 4];
            ah[mt][3] = Sh[(prow + 8) * SHP + kpg + 4];
            al[mt][0] = Sl[prow * SHP + kpg];
            al[mt][1] = Sl[(prow + 8) * SHP + kpg];
            al[mt][2] = Sl[prow * SHP + kpg + 4];
            al[mt][3] = Sl[(prow + 8) * SHP + kpg + 4];
        }
#pragma unroll
        for (int sl = 0; sl < 2; sl++) {
            const int nt = warp + 8 * sl;
            if (nt < NTILE) {
                const int fi = (nt * NKS + ks) * 32 + lane;
                ull wh = __ldg(WhG + fi);
                ull wl = __ldg(WlG + fi);
                u32 bh0 = (u32)wh, bh1 = (u32)(wh >> 32);
                u32 bl0 = (u32)wl, bl1 = (u32)(wl >> 32);
#pragma unroll
                for (int mt = 0; mt < 2; mt++) {
                    mma_bf16(acc[mt][sl], ah[mt], bh0, bh1);   // hi*hi
                    mma_bf16(acc[mt][sl], al[mt], bh0, bh1);   // lo*hi
                    mma_bf16(acc[mt][sl], ah[mt], bl0, bl1);   // hi*lo
                }
            }
        }
    }

    float G = 0.0f;
#pragma unroll
    for (int t2 = 0; t2 < NSTEPS; t2++) G = __fadd_rn(__fmul_rn(beta2, G), 1.0f);

#pragma unroll
    for (int mt = 0; mt < 2; mt++) {
#pragma unroll
        for (int sl = 0; sl < 2; sl++) {
            const int nt = warp + 8 * sl;
            if (nt < NTILE) {
#pragma unroll
                for (int e = 0; e < 4; e++) {
                    const int pp = blockIdx.x * NP + mt * 16 + g + (e >> 1) * 8;
                    const int n = nt * 8 + 2 * t + (e & 1);
                    if (pp < NPAIR && n < PDIM)
                        g_U[pp * UPITCH + n] = acc[mt][sl][e] + __ldg(b2 + n) * G;
                }
            }
        }
    }
}

// ---------------------------------------------------------------------------
// Kernel C: out[b,:] = U[pair(b),:]. One warp per output row.
// ---------------------------------------------------------------------------
__global__ void __launch_bounds__(256) scatter_kernel(
    const int* __restrict__ x, float* __restrict__ out, int B)
{
    int warp = blockIdx.x * 8 + (threadIdx.x >> 5);
    int lane = threadIdx.x & 31;
    if (warp >= B) return;
    int x0 = __ldg(x + 2 * warp);
    int x1 = __ldg(x + 2 * warp + 1);
    const float* u = g_U + (size_t)(x0 * PDIM + x1) * UPITCH;
    float* o = out + (size_t)warp * PDIM;
#pragma unroll
    for (int j = 0; j < 3; j++) o[lane + 32 * j] = u[lane + 32 * j];
    if (lane == 0) o[96] = u[96];
}

// ---------------------------------------------------------------------------
extern "C" void kernel_launch(void* const* d_in, const int* in_sizes, int n_in,
                              void* d_out, int out_size)
{
    const int*   x     = (const int*)  d_in[0];
    const float* E     = (const float*)d_in[1];
    const float* W1    = (const float*)d_in[2];
    const float* b1    = (const float*)d_in[3];
    const float* W2    = (const float*)d_in[4];
    const float* b2    = (const float*)d_in[5];
    const float* beta1 = (const float*)d_in[6];
    const float* beta2 = (const float*)d_in[7];
    const float* thr1  = (const float*)d_in[8];
    // thr2 unused in forward (lif2 reset='none'; output is mem2).

    const int B = in_sizes[0] / 2;

    const int psmemB = (PVT * (HIDDEN / 4) + PJT * W1PIT) * (int)sizeof(float4); // 164864
    cudaFuncSetAttribute(precompute_kernel,
                         cudaFuncAttributeMaxDynamicSharedMemorySize, psmemB);

    const int smemB = (2 * NP * SHP + 384) * (int)sizeof(u32);   // 68096 B
    cudaFuncSetAttribute(pair_kernel, cudaFuncAttributeMaxDynamicSharedMemorySize, smemB);

    precompute_kernel<<<dim3(8, 7, 2), 256, psmemB>>>(E, W1, W2, beta2);
    pair_kernel<<<(NPAIR + NP - 1) / NP, 256, smemB>>>(b1, b2, beta1, beta2, thr1);
    scatter_kernel<<<(B + 7) / 8, 256>>>(x, (float*)d_out, B);
}